// round 5
// baseline (speedup 1.0000x reference)
#include <cuda_runtime.h>
#include <cuda_fp16.h>
#include <cstdint>

#define BATCH 32768
#define IN1   784
#define KPAD  832          // 13 * 64
#define HID   256
#define OUT   10
#define W1B   98
#define W2B   32
#define KC    64
#define NCHUNK 13
#define BM    128
#define NTHR  320          // 8 compute warps + 2 producer warps
#define NST   3

// -------- device scratch (allocation-free rule) --------
__device__ __align__(16) __half g_w1h[HID * KPAD];   // [256][832] fp16 {-1,0,+1}
__device__ float g_w2f[OUT * HID];                   // [10][256] fp32 (incl alpha2)

// -------- shared memory layout (bytes) --------
#define SM_A(s) ((s) * 16384)              // 128 x 64 fp16 = 16KB x3
#define SM_B(s) (49152 + (s) * 32768)      // 256 x 64 fp16 = 32KB x3
#define SM_W2   147456                     // 10KB
#define SM_BAR  157696                     // full[3] @ +0, empty[3] @ +24
#define SM_PART 0                          // epilogue alias over A buffers (20KB)
#define SMEM_TOTAL 157760

// -------- helpers --------
__device__ __forceinline__ uint32_t smem_u32(const void* p) {
    uint32_t a;
    asm("{ .reg .u64 t; cvta.to.shared.u64 t, %1; cvt.u32.u64 %0, t; }" : "=r"(a) : "l"(p));
    return a;
}
__device__ __forceinline__ uint32_t swz(uint32_t off) {  // SW128
    return off ^ ((off >> 3) & 0x70);
}
__device__ __forceinline__ uint32_t pkh(__half a, __half b) {
    __half2 t(a, b);
    return *reinterpret_cast<uint32_t*>(&t);
}
__device__ __forceinline__ void ldm_x4(uint32_t& r0, uint32_t& r1, uint32_t& r2, uint32_t& r3,
                                       uint32_t addr) {
    asm volatile("ldmatrix.sync.aligned.m8n8.x4.shared.b16 {%0,%1,%2,%3}, [%4];"
                 : "=r"(r0), "=r"(r1), "=r"(r2), "=r"(r3) : "r"(addr));
}
__device__ __forceinline__ void mma16816(float* d, const uint32_t* a, const uint32_t* b) {
    asm volatile(
        "mma.sync.aligned.m16n8k16.row.col.f32.f16.f16.f32 "
        "{%0,%1,%2,%3}, {%4,%5,%6,%7}, {%8,%9}, {%0,%1,%2,%3};"
        : "+f"(d[0]), "+f"(d[1]), "+f"(d[2]), "+f"(d[3])
        : "r"(a[0]), "r"(a[1]), "r"(a[2]), "r"(a[3]), "r"(b[0]), "r"(b[1]));
}
__device__ __forceinline__ void cpa16(uint32_t dst, const void* src) {
    asm volatile("cp.async.cg.shared.global [%0], [%1], 16;" :: "r"(dst), "l"(src) : "memory");
}
__device__ __forceinline__ void mbar_init(uint32_t mbar, uint32_t cnt) {
    asm volatile("mbarrier.init.shared.b64 [%0], %1;" :: "r"(mbar), "r"(cnt) : "memory");
}
__device__ __forceinline__ void mbar_arrive(uint32_t mbar) {
    asm volatile("mbarrier.arrive.shared.b64 _, [%0];" :: "r"(mbar) : "memory");
}
__device__ __forceinline__ void cpasync_arrive_noinc(uint32_t mbar) {
    asm volatile("cp.async.mbarrier.arrive.noinc.shared.b64 [%0];" :: "r"(mbar) : "memory");
}
__device__ __forceinline__ void mbar_wait(uint32_t mbar, uint32_t parity) {
    asm volatile(
        "{\n\t.reg .pred P;\n"
        "WL_%=:\n\t"
        "mbarrier.try_wait.parity.acquire.cta.shared::cta.b64 P, [%0], %1, 0x989680;\n\t"
        "@P bra.uni WD_%=;\n\t"
        "bra.uni WL_%=;\n"
        "WD_%=:\n\t}"
        :: "r"(mbar), "r"(parity) : "memory");
}

// ---------------------------------------------------------------------------
__global__ void unpack_all(const int* __restrict__ w1p, const int* __restrict__ m1p,
                           const int* __restrict__ w2p, const int* __restrict__ m2p,
                           const float* __restrict__ a2) {
    int idx = blockIdx.x * 256 + threadIdx.x;
    if (idx < HID * KPAD) {
        int o = idx / KPAD, i = idx - o * KPAD;
        float v = 0.0f;
        if (i < IN1) {
            int sh = 7 - (i & 7);
            int wb = (w1p[o * W1B + (i >> 3)] >> sh) & 1;
            int mb = (m1p[o * W1B + (i >> 3)] >> sh) & 1;
            v = (2.0f * (float)wb - 1.0f) * (float)mb;
        }
        g_w1h[idx] = __float2half_rn(v);
    } else {
        int j = idx - HID * KPAD;
        if (j < OUT * HID) {
            int o = j / HID, i = j - o * HID;
            int sh = 7 - (i & 7);
            int wb = (w2p[o * W2B + (i >> 3)] >> sh) & 1;
            int mb = (m2p[o * W2B + (i >> 3)] >> sh) & 1;
            g_w2f[j] = (2.0f * (float)wb - 1.0f) * (float)mb * a2[0];
        }
    }
}

// ---------------------------------------------------------------------------
// Warp-specialized fused kernel.
//   warps 0-7 : consumers, D[128,256] via mma.sync fp16 + fused layer-2 epilogue
//   warps 8-9 : producers, LDG x -> cvt fp16 -> STS (A) and cp.async (B),
//               3-stage mbarrier ring.
// ---------------------------------------------------------------------------
__global__ void __launch_bounds__(NTHR, 1)
fused(const float* __restrict__ x, const float* __restrict__ alpha1,
      float* __restrict__ out) {
    extern __shared__ char smem[];
    const uint32_t sb = smem_u32(smem);
    const int tid = threadIdx.x, wid = tid >> 5, lane = tid & 31;
    const int bm = blockIdx.x * BM;
    const float* __restrict__ xb = x + (size_t)bm * IN1;

    if (tid == 0) {
        #pragma unroll
        for (int s = 0; s < NST; ++s) {
            mbar_init(sb + SM_BAR + s * 8, 128);        // full: 64 cp + 64 sts arrivals
            mbar_init(sb + SM_BAR + 24 + s * 8, 256);   // empty: 256 consumer arrivals
        }
    }
    for (int i = tid; i < OUT * HID; i += NTHR)
        reinterpret_cast<float*>(smem + SM_W2)[i] = g_w2f[i];
    __syncthreads();

    if (wid >= 8) {
        // ================= PRODUCER (64 threads) =================
        const int ptid = tid - 256;
        int st = 0, ph = 1;                    // parity-1 trick: first NST waits pass
        for (int c = 0; c < NCHUNK; ++c) {
            mbar_wait(sb + SM_BAR + 24 + st * 8, ph);   // wait empty[st]
            const int kt = c * KC;
            // ---- B tile: 2048 x 16B granules via cp.async ----
            #pragma unroll
            for (int it = 0; it < 32; ++it) {
                int idx = ptid + it * 64;
                int n = idx >> 3, u = idx & 7;
                cpa16(sb + SM_B(st) + swz((uint32_t)(n * 128 + u * 16)),
                      g_w1h + (size_t)n * KPAD + kt + u * 8);
            }
            cpasync_arrive_noinc(sb + SM_BAR + st * 8);
            // ---- A tile: 2048 float4, LDG -> fp16 -> STS (swizzled) ----
            #pragma unroll
            for (int blk = 0; blk < 4; ++blk) {
                float4 v[8];
                #pragma unroll
                for (int it = 0; it < 8; ++it) {
                    int idx = ptid + (blk * 8 + it) * 64;
                    int row = idx >> 4, f = idx & 15;
                    int col = kt + f * 4;
                    v[it] = (col < IN1)
                        ? *reinterpret_cast<const float4*>(xb + (size_t)row * IN1 + col)
                        : make_float4(0.f, 0.f, 0.f, 0.f);
                }
                #pragma unroll
                for (int it = 0; it < 8; ++it) {
                    int idx = ptid + (blk * 8 + it) * 64;
                    int row = idx >> 4, f = idx & 15;
                    uint32_t sw = swz((uint32_t)(row * 128 + f * 8));
                    *reinterpret_cast<uint2*>(smem + SM_A(st) + sw) =
                        make_uint2(pkh(__float2half_rn(v[it].x), __float2half_rn(v[it].y)),
                                   pkh(__float2half_rn(v[it].z), __float2half_rn(v[it].w)));
                }
            }
            mbar_arrive(sb + SM_BAR + st * 8);          // full[st] (release: STS visible)
            if (++st == NST) { st = 0; ph ^= 1; }
        }
    } else {
        // ================= CONSUMER (256 threads) =================
        const int wm = wid >> 2, wn = wid & 3;          // 2 x 4 warp grid, 64x64 tiles
        const int g = lane >> 3, lr = lane & 7;
        const float a1v = alpha1[0];

        float acc[4][8][4];
        #pragma unroll
        for (int i = 0; i < 4; ++i)
            #pragma unroll
            for (int j = 0; j < 8; ++j)
                #pragma unroll
                for (int r = 0; r < 4; ++r) acc[i][j][r] = 0.0f;

        int st = 0, ph = 0;
        for (int c = 0; c < NCHUNK; ++c) {
            mbar_wait(sb + SM_BAR + st * 8, ph);        // wait full[st] (acquire)
            #pragma unroll
            for (int ks = 0; ks < 4; ++ks) {
                uint32_t b[8][2];
                #pragma unroll
                for (int p = 0; p < 4; ++p) {
                    int n  = wn * 64 + p * 16 + ((g & 2) ? 8 : 0) + lr;
                    int kk = ks * 16 + ((g & 1) ? 8 : 0);
                    ldm_x4(b[2 * p][0], b[2 * p][1], b[2 * p + 1][0], b[2 * p + 1][1],
                           sb + SM_B(st) + swz((uint32_t)(n * 128 + kk * 2)));
                }
                uint32_t a[4][4];
                #pragma unroll
                for (int i = 0; i < 4; ++i) {
                    int row = wm * 64 + i * 16 + ((g & 1) ? 8 : 0) + lr;
                    int kk  = ks * 16 + ((g & 2) ? 8 : 0);
                    ldm_x4(a[i][0], a[i][1], a[i][2], a[i][3],
                           sb + SM_A(st) + swz((uint32_t)(row * 128 + kk * 2)));
                }
                #pragma unroll
                for (int i = 0; i < 4; ++i)
                    #pragma unroll
                    for (int j = 0; j < 8; ++j) mma16816(acc[i][j], a[i], b[j]);
            }
            mbar_arrive(sb + SM_BAR + 24 + st * 8);     // empty[st]
            if (++st == NST) { st = 0; ph ^= 1; }
        }

        // ---- epilogue part 1: relu + per-warp layer-2 partials ----
        #pragma unroll
        for (int i = 0; i < 4; ++i)
            #pragma unroll
            for (int j = 0; j < 8; ++j)
                #pragma unroll
                for (int r = 0; r < 4; ++r)
                    acc[i][j][r] = fmaxf(a1v * acc[i][j][r], 0.0f);

        __syncthreads();                                // (A) join producers, free A smem
        const float* w2s = reinterpret_cast<const float*>(smem + SM_W2);
        float* part = reinterpret_cast<float*>(smem + SM_PART);
        const int q = lane & 3, gq = lane >> 2;

        #pragma unroll
        for (int o = 0; o < OUT; ++o) {
            float w2v[8][2];
            #pragma unroll
            for (int j = 0; j < 8; ++j) {
                w2v[j][0] = w2s[o * HID + wn * 64 + j * 8 + q * 2];
                w2v[j][1] = w2s[o * HID + wn * 64 + j * 8 + q * 2 + 1];
            }
            #pragma unroll
            for (int i = 0; i < 4; ++i)
                #pragma unroll
                for (int h2 = 0; h2 < 2; ++h2) {
                    float s = 0.0f;
                    #pragma unroll
                    for (int j = 0; j < 8; ++j)
                        s += acc[i][j][h2 * 2] * w2v[j][0] + acc[i][j][h2 * 2 + 1] * w2v[j][1];
                    s += __shfl_xor_sync(0xffffffffu, s, 1);
                    s += __shfl_xor_sync(0xffffffffu, s, 2);
                    if (q == 0) {
                        int row = wm * 64 + i * 16 + h2 * 8 + gq;
                        part[wn * (BM * OUT) + row * OUT + o] = s;
                    }
                }
        }
    }

    if (wid >= 8) __syncthreads();                      // producers join barrier (A)
    __syncthreads();                                    // (B) partials visible

    {
        float* part = reinterpret_cast<float*>(smem + SM_PART);
        for (int idx = tid; idx < BM * OUT; idx += NTHR) {
            float v = part[idx] + part[BM * OUT + idx] +
                      part[2 * BM * OUT + idx] + part[3 * BM * OUT + idx];
            out[(size_t)bm * OUT + idx] = v;
        }
    }
}

// ---------------------------------------------------------------------------
extern "C" void kernel_launch(void* const* d_in, const int* in_sizes, int n_in,
                              void* d_out, int out_size) {
    const float* x   = (const float*)d_in[0];
    const int*   w1p = (const int*)d_in[1];
    const int*   m1p = (const int*)d_in[2];
    const float* a1  = (const float*)d_in[3];
    const int*   w2p = (const int*)d_in[4];
    const int*   m2p = (const int*)d_in[5];
    const float* a2  = (const float*)d_in[6];
    float* out = (float*)d_out;

    cudaFuncSetAttribute(fused, cudaFuncAttributeMaxDynamicSharedMemorySize, SMEM_TOTAL);

    int total = HID * KPAD + OUT * HID;
    unpack_all<<<(total + 255) / 256, 256>>>(w1p, m1p, w2p, m2p, a2);
    fused<<<BATCH / BM, NTHR, SMEM_TOTAL>>>(x, a1, out);
}

// round 6
// speedup vs baseline: 1.5143x; 1.5143x over previous
#include <cuda_runtime.h>
#include <cuda_fp16.h>
#include <cstdint>

#define BATCH 32768
#define IN1   784
#define KPAD  832          // 13 * 64
#define HID   256
#define OUT   10
#define W1B   98
#define W2B   32
#define KC    64
#define NCHUNK 13
#define BM    64
#define NTHR  256

// -------- device scratch (allocation-free rule) --------
__device__ __align__(16) __half g_w1h[HID * KPAD];   // [256][832] fp16 {-1,0,+1}
__device__ float g_w2f[OUT * HID];                   // [10][256] fp32 (incl alpha2)

// -------- shared memory layout (bytes) --------
#define SM_A(s) ((s) * 8192)               // 64 x 64 fp16 = 8KB x2
#define SM_B(s) (16384 + (s) * 32768)      // 256 x 64 fp16 = 32KB x2
#define SM_W2   81920                      // 10KB
#define SM_PART 0                          // epilogue alias over A buffers (10KB)
#define SMEM_TOTAL (81920 + OUT * HID * 4)

// -------- helpers --------
__device__ __forceinline__ uint32_t smem_u32(const void* p) {
    uint32_t a;
    asm("{ .reg .u64 t; cvta.to.shared.u64 t, %1; cvt.u32.u64 %0, t; }" : "=r"(a) : "l"(p));
    return a;
}
__device__ __forceinline__ uint32_t swz(uint32_t off) {  // SW128
    return off ^ ((off >> 3) & 0x70);
}
__device__ __forceinline__ uint32_t pkh(__half a, __half b) {
    __half2 t(a, b);
    return *reinterpret_cast<uint32_t*>(&t);
}
__device__ __forceinline__ void ldm_x4(uint32_t& r0, uint32_t& r1, uint32_t& r2, uint32_t& r3,
                                       uint32_t addr) {
    asm volatile("ldmatrix.sync.aligned.m8n8.x4.shared.b16 {%0,%1,%2,%3}, [%4];"
                 : "=r"(r0), "=r"(r1), "=r"(r2), "=r"(r3) : "r"(addr));
}
__device__ __forceinline__ void mma16816(float* d, const uint32_t* a, const uint32_t* b) {
    asm volatile(
        "mma.sync.aligned.m16n8k16.row.col.f32.f16.f16.f32 "
        "{%0,%1,%2,%3}, {%4,%5,%6,%7}, {%8,%9}, {%0,%1,%2,%3};"
        : "+f"(d[0]), "+f"(d[1]), "+f"(d[2]), "+f"(d[3])
        : "r"(a[0]), "r"(a[1]), "r"(a[2]), "r"(a[3]), "r"(b[0]), "r"(b[1]));
}
__device__ __forceinline__ void cpa16(uint32_t dst, const void* src) {
    asm volatile("cp.async.cg.shared.global [%0], [%1], 16;" :: "r"(dst), "l"(src) : "memory");
}

// ---------------------------------------------------------------------------
__global__ void unpack_all(const int* __restrict__ w1p, const int* __restrict__ m1p,
                           const int* __restrict__ w2p, const int* __restrict__ m2p,
                           const float* __restrict__ a2) {
    int idx = blockIdx.x * 256 + threadIdx.x;
    if (idx < HID * KPAD) {
        int o = idx / KPAD, i = idx - o * KPAD;
        float v = 0.0f;
        if (i < IN1) {
            int sh = 7 - (i & 7);
            int wb = (w1p[o * W1B + (i >> 3)] >> sh) & 1;
            int mb = (m1p[o * W1B + (i >> 3)] >> sh) & 1;
            v = (2.0f * (float)wb - 1.0f) * (float)mb;
        }
        g_w1h[idx] = __float2half_rn(v);
    } else {
        int j = idx - HID * KPAD;
        if (j < OUT * HID) {
            int o = j / HID, i = j - o * HID;
            int sh = 7 - (i & 7);
            int wb = (w2p[o * W2B + (i >> 3)] >> sh) & 1;
            int mb = (m2p[o * W2B + (i >> 3)] >> sh) & 1;
            g_w2f[j] = (2.0f * (float)wb - 1.0f) * (float)mb * a2[0];
        }
    }
}

// ---------------------------------------------------------------------------
// Fused, 2 CTAs/SM: D[64,256] = x_tile @ w1^T (fp16 mma, fp32 acc),
// epilogue out = relu(alpha1*D) @ w2^T.
// ---------------------------------------------------------------------------
__global__ void __launch_bounds__(NTHR, 2)
fused(const float* __restrict__ x, const float* __restrict__ alpha1,
      float* __restrict__ out) {
    extern __shared__ char smem[];
    const uint32_t sb = smem_u32(smem);
    const int tid = threadIdx.x, wid = tid >> 5, lane = tid & 31;
    const int wm = wid >> 2, wn = wid & 3;        // 2x4 warp grid, 32x64 warp tiles
    const int bm = blockIdx.x * BM;
    const float* __restrict__ xb = x + (size_t)bm * IN1;

    for (int i = tid; i < OUT * HID; i += NTHR)
        reinterpret_cast<float*>(smem + SM_W2)[i] = g_w2f[i];

    float acc[2][8][4];
    #pragma unroll
    for (int i = 0; i < 2; ++i)
        #pragma unroll
        for (int j = 0; j < 8; ++j)
            #pragma unroll
            for (int r = 0; r < 4; ++r) acc[i][j][r] = 0.0f;

    float4 sa[4];                                  // x staging (1 chunk = 4 float4/thread)
    const int g = lane >> 3, lr = lane & 7;

    auto loadA = [&](int c) {
        const int kt = c * KC;
        #pragma unroll
        for (int it = 0; it < 4; ++it) {
            int idx = tid + it * NTHR;             // 0..1023 float4 slots (64 rows x 16)
            int row = idx >> 4, f = idx & 15;
            int col = kt + f * 4;
            sa[it] = (col < IN1)
                ? *reinterpret_cast<const float4*>(xb + (size_t)row * IN1 + col)
                : make_float4(0.f, 0.f, 0.f, 0.f);
        }
    };
    auto storeA = [&](int s) {
        #pragma unroll
        for (int it = 0; it < 4; ++it) {
            int idx = tid + it * NTHR;
            int row = idx >> 4, f = idx & 15;
            float4 v = sa[it];
            uint32_t sw = swz((uint32_t)(row * 128 + f * 8));
            *reinterpret_cast<uint2*>(smem + SM_A(s) + sw) =
                make_uint2(pkh(__float2half_rn(v.x), __float2half_rn(v.y)),
                           pkh(__float2half_rn(v.z), __float2half_rn(v.w)));
        }
    };
    auto issueB = [&](int c, int s) {
        const int kt = c * KC;
        #pragma unroll
        for (int it = 0; it < 8; ++it) {
            int idx = tid + it * NTHR;             // 0..2047 16B granules (256 rows x 8)
            int n = idx >> 3, u = idx & 7;
            cpa16(sb + SM_B(s) + swz((uint32_t)(n * 128 + u * 16)),
                  g_w1h + (size_t)n * KPAD + kt + u * 8);
        }
        asm volatile("cp.async.commit_group;" ::: "memory");
    };
    auto compute = [&](int s) {
        #pragma unroll
        for (int ks = 0; ks < 4; ++ks) {
            uint32_t b[8][2];
            #pragma unroll
            for (int p = 0; p < 4; ++p) {
                int n  = wn * 64 + p * 16 + ((g & 2) ? 8 : 0) + lr;
                int kk = ks * 16 + ((g & 1) ? 8 : 0);
                ldm_x4(b[2 * p][0], b[2 * p][1], b[2 * p + 1][0], b[2 * p + 1][1],
                       sb + SM_B(s) + swz((uint32_t)(n * 128 + kk * 2)));
            }
            uint32_t a[2][4];
            #pragma unroll
            for (int i = 0; i < 2; ++i) {
                int row = wm * 32 + i * 16 + ((g & 1) ? 8 : 0) + lr;
                int kk  = ks * 16 + ((g & 2) ? 8 : 0);
                ldm_x4(a[i][0], a[i][1], a[i][2], a[i][3],
                       sb + SM_A(s) + swz((uint32_t)(row * 128 + kk * 2)));
            }
            #pragma unroll
            for (int i = 0; i < 2; ++i)
                #pragma unroll
                for (int j = 0; j < 8; ++j) mma16816(acc[i][j], a[i], b[j]);
        }
    };

    // ---- prologue: B0 in flight, A0 stored, x(1) staged ----
    issueB(0, 0);
    loadA(0); storeA(0);
    loadA(1);
    asm volatile("cp.async.wait_group 0;" ::: "memory");
    __syncthreads();

    // ---- mainloop: iter c has A[c&1], B[c&1] ready; sa = x(c+1) ----
    for (int c = 0; c < NCHUNK; ++c) {
        if (c + 1 < NCHUNK) {
            issueB(c + 1, (c + 1) & 1);   // stage freed at last sync
            storeA((c + 1) & 1);
        }
        if (c + 2 < NCHUNK) loadA(c + 2);
        compute(c & 1);
        if (c + 1 < NCHUNK) {
            asm volatile("cp.async.wait_group 0;" ::: "memory");
            __syncthreads();
        }
    }

    // ---- epilogue: out = relu(a1*acc) @ w2^T ----
    __syncthreads();                        // before aliasing A smem
    const float a1v = alpha1[0];
    #pragma unroll
    for (int i = 0; i < 2; ++i)
        #pragma unroll
        for (int j = 0; j < 8; ++j)
            #pragma unroll
            for (int r = 0; r < 4; ++r)
                acc[i][j][r] = fmaxf(a1v * acc[i][j][r], 0.0f);

    const float* w2s = reinterpret_cast<const float*>(smem + SM_W2);
    float* part = reinterpret_cast<float*>(smem + SM_PART);
    const int q = lane & 3, gq = lane >> 2;

    #pragma unroll
    for (int o = 0; o < OUT; ++o) {
        float w2v[8][2];
        #pragma unroll
        for (int j = 0; j < 8; ++j) {
            w2v[j][0] = w2s[o * HID + wn * 64 + j * 8 + q * 2];
            w2v[j][1] = w2s[o * HID + wn * 64 + j * 8 + q * 2 + 1];
        }
        #pragma unroll
        for (int i = 0; i < 2; ++i)
            #pragma unroll
            for (int h2 = 0; h2 < 2; ++h2) {
                float s = 0.0f;
                #pragma unroll
                for (int j = 0; j < 8; ++j)
                    s += acc[i][j][h2 * 2] * w2v[j][0] + acc[i][j][h2 * 2 + 1] * w2v[j][1];
                s += __shfl_xor_sync(0xffffffffu, s, 1);
                s += __shfl_xor_sync(0xffffffffu, s, 2);
                if (q == 0) {
                    int row = wm * 32 + i * 16 + h2 * 8 + gq;
                    part[wn * (BM * OUT) + row * OUT + o] = s;
                }
            }
    }
    __syncthreads();

    for (int idx = tid; idx < BM * OUT; idx += NTHR) {
        float v = part[idx] + part[BM * OUT + idx] +
                  part[2 * BM * OUT + idx] + part[3 * BM * OUT + idx];
        out[(size_t)bm * OUT + idx] = v;
    }
}

// ---------------------------------------------------------------------------
extern "C" void kernel_launch(void* const* d_in, const int* in_sizes, int n_in,
                              void* d_out, int out_size) {
    const float* x   = (const float*)d_in[0];
    const int*   w1p = (const int*)d_in[1];
    const int*   m1p = (const int*)d_in[2];
    const float* a1  = (const float*)d_in[3];
    const int*   w2p = (const int*)d_in[4];
    const int*   m2p = (const int*)d_in[5];
    const float* a2  = (const float*)d_in[6];
    float* out = (float*)d_out;

    cudaFuncSetAttribute(fused, cudaFuncAttributeMaxDynamicSharedMemorySize, SMEM_TOTAL);

    int total = HID * KPAD + OUT * HID;
    unpack_all<<<(total + 255) / 256, 256>>>(w1p, m1p, w2p, m2p, a2);
    fused<<<BATCH / BM, NTHR, SMEM_TOTAL>>>(x, a1, out);
}